// round 10
// baseline (speedup 1.0000x reference)
#include <cuda_runtime.h>
#include <cuda_bf16.h>
#include <cstdint>

#define N_NODES 50000
#define N_EDGES 800000
#define IN_DIM 128
#define OUT_DIM 64
#define NUM_HEADS 4
#define MAXDEG 96

// Scratch (no cudaMalloc allowed)
__device__ float g_Whi[IN_DIM * OUT_DIM];           // tf32-rounded hi part of Wavg
__device__ float g_Wlo[IN_DIM * OUT_DIM];           // tf32-rounded residual
__device__ float g_hp[N_NODES * OUT_DIM];           // 12.8 MB
__device__ int   g_deg[N_NODES];                    // 200 KB
__device__ int   g_adj[(size_t)N_NODES * MAXDEG];   // 19.2 MB

// ---------------------------------------------------------------------------
// tf32 helpers
// ---------------------------------------------------------------------------
__device__ __forceinline__ void split_tf32(float x, uint32_t& hi, uint32_t& lo) {
    asm("cvt.rna.tf32.f32 %0, %1;" : "=r"(hi) : "f"(x));
    float r = x - __uint_as_float(hi);
    asm("cvt.rna.tf32.f32 %0, %1;" : "=r"(lo) : "f"(r));
}

#define MMA_TF32(D, A0, A1, A2, A3, B0, B1)                                    \
    asm("mma.sync.aligned.m16n8k8.row.col.f32.tf32.tf32.f32 "                  \
        "{%0,%1,%2,%3}, {%4,%5,%6,%7}, {%8,%9}, {%0,%1,%2,%3};"                \
        : "+f"((D)[0]), "+f"((D)[1]), "+f"((D)[2]), "+f"((D)[3])               \
        : "r"(A0), "r"(A1), "r"(A2), "r"(A3), "r"(B0), "r"(B1))

// ---------------------------------------------------------------------------
// Kernel 1: Wavg = mean_k W[k], pre-split into tf32 hi/lo parts
// ---------------------------------------------------------------------------
__global__ void wavg_kernel(const float* __restrict__ W) {
    int i = blockIdx.x * blockDim.x + threadIdx.x;
    if (i < IN_DIM * OUT_DIM) {
        float avg = 0.25f * (W[i] + W[IN_DIM * OUT_DIM + i] +
                             W[2 * IN_DIM * OUT_DIM + i] + W[3 * IN_DIM * OUT_DIM + i]);
        uint32_t hi, lo;
        split_tf32(avg, hi, lo);
        g_Whi[i] = __uint_as_float(hi);
        g_Wlo[i] = __uint_as_float(lo);
    }
}

// ---------------------------------------------------------------------------
// Kernel 2: zero per-node degree counters (vectorized)
// ---------------------------------------------------------------------------
__global__ void zero_deg_kernel(int n4) {
    int i = blockIdx.x * blockDim.x + threadIdx.x;
    if (i < n4) ((int4*)g_deg)[i] = make_int4(0, 0, 0, 0);
}

// ---------------------------------------------------------------------------
// Kernel 3: build padded adjacency, 4 edges per thread for MLP on the
// ATOMG->STG dependency chains.
// ---------------------------------------------------------------------------
__global__ __launch_bounds__(256) void build_adj_kernel(const int* __restrict__ src,
                                                        const int* __restrict__ dst,
                                                        int n_edges) {
    int g = blockIdx.x * blockDim.x + threadIdx.x;
    int nG = n_edges >> 2;
    if (g < nG) {
        int4 s = ((const int4*)src)[g];
        int4 d = ((const int4*)dst)[g];
        int p0 = atomicAdd(&g_deg[d.x], 1);
        int p1 = atomicAdd(&g_deg[d.y], 1);
        int p2 = atomicAdd(&g_deg[d.z], 1);
        int p3 = atomicAdd(&g_deg[d.w], 1);
        if (p0 < MAXDEG) g_adj[(size_t)d.x * MAXDEG + p0] = s.x;
        if (p1 < MAXDEG) g_adj[(size_t)d.y * MAXDEG + p1] = s.y;
        if (p2 < MAXDEG) g_adj[(size_t)d.z * MAXDEG + p2] = s.z;
        if (p3 < MAXDEG) g_adj[(size_t)d.w * MAXDEG + p3] = s.w;
    } else if (g == nG) {
        for (int e = nG * 4; e < n_edges; e++) {
            int d = dst[e];
            int pos = atomicAdd(&g_deg[d], 1);
            if (pos < MAXDEG) g_adj[(size_t)d * MAXDEG + pos] = src[e];
        }
    }
}

// ---------------------------------------------------------------------------
// Kernel 4: hp = h @ Wavg  via mma.sync.m16n8k8.tf32 with 3xTF32 precision.
// (R8 version: measured 25.7us.) Block = 128 rows x 64 cols, 256 threads =
// 8 warps (4 along M x 2 along N). A staged in smem, B via __ldg.
// ---------------------------------------------------------------------------
#define BM 128
#define KPH 64
#define PA 68     // sA pitch in floats -> fragment bank = (4*gID + tig) % 32, all distinct

__global__ __launch_bounds__(256) void gemm_kernel(const float* __restrict__ h,
                                                   int n_nodes) {
    __shared__ float sA[BM * PA];    // ~34.8 KB

    int tid  = threadIdx.x;
    int lane = tid & 31;
    int wid  = tid >> 5;       // 0..7
    int wm   = wid & 3;        // M strip: rows wm*32..wm*32+31
    int wn   = wid >> 2;       // N strip: cols wn*32..wn*32+31
    int gID  = lane >> 2;      // 0..7
    int tig  = lane & 3;       // 0..3
    int rowBase = blockIdx.x * BM;

    float d[2][4][4];          // [mtile][ntile][frag]
    #pragma unroll
    for (int mt = 0; mt < 2; mt++)
        #pragma unroll
        for (int nt = 0; nt < 4; nt++)
            #pragma unroll
            for (int q = 0; q < 4; q++) d[mt][nt][q] = 0.f;

    #pragma unroll
    for (int ph = 0; ph < 2; ph++) {
        // stage h slab: 128 rows x 64 floats = 2048 float4, 8 per thread
        #pragma unroll
        for (int it = 0; it < 8; it++) {
            int item = tid + it * 256;
            int r = item >> 4;          // 16 float4 per row
            int c = item & 15;
            int row = rowBase + r;
            float4 v = make_float4(0.f, 0.f, 0.f, 0.f);
            if (row < n_nodes)
                v = ((const float4*)(h + (size_t)row * IN_DIM + ph * KPH))[c];
            *(float4*)(sA + r * PA + 4 * c) = v;
        }
        __syncthreads();

        #pragma unroll
        for (int kk = 0; kk < KPH; kk += 8) {
            int kg = ph * KPH + kk + tig;    // global k of b0 row

            // B fragments hi/lo for 4 n-tiles (L1-resident __ldg)
            uint32_t bhi[4][2], blo[4][2];
            #pragma unroll
            for (int nt = 0; nt < 4; nt++) {
                int ncol = wn * 32 + nt * 8 + gID;
                int i0 = kg * OUT_DIM + ncol;
                int i1 = (kg + 4) * OUT_DIM + ncol;
                bhi[nt][0] = __float_as_uint(__ldg(g_Whi + i0));
                bhi[nt][1] = __float_as_uint(__ldg(g_Whi + i1));
                blo[nt][0] = __float_as_uint(__ldg(g_Wlo + i0));
                blo[nt][1] = __float_as_uint(__ldg(g_Wlo + i1));
            }

            #pragma unroll
            for (int mt = 0; mt < 2; mt++) {
                const float* ab = sA + (wm * 32 + mt * 16 + gID) * PA + kk + tig;
                float a0 = ab[0];
                float a1 = ab[8 * PA];
                float a2 = ab[4];
                float a3 = ab[8 * PA + 4];
                uint32_t ah[4], al[4];
                split_tf32(a0, ah[0], al[0]);
                split_tf32(a1, ah[1], al[1]);
                split_tf32(a2, ah[2], al[2]);
                split_tf32(a3, ah[3], al[3]);

                #pragma unroll
                for (int nt = 0; nt < 4; nt++) {
                    MMA_TF32(d[mt][nt], ah[0], ah[1], ah[2], ah[3],
                             bhi[nt][0], bhi[nt][1]);
                    MMA_TF32(d[mt][nt], al[0], al[1], al[2], al[3],
                             bhi[nt][0], bhi[nt][1]);
                    MMA_TF32(d[mt][nt], ah[0], ah[1], ah[2], ah[3],
                             blo[nt][0], blo[nt][1]);
                }
            }
        }
        __syncthreads();
    }

    // epilogue: each thread owns (row gID / gID+8, col tig*2..tig*2+1) per tile
    #pragma unroll
    for (int mt = 0; mt < 2; mt++) {
        int r0 = rowBase + wm * 32 + mt * 16 + gID;
        #pragma unroll
        for (int nt = 0; nt < 4; nt++) {
            int col = wn * 32 + nt * 8 + tig * 2;
            if (r0 < n_nodes)
                *(float2*)(g_hp + (size_t)r0 * OUT_DIM + col) =
                    make_float2(d[mt][nt][0], d[mt][nt][1]);
            if (r0 + 8 < n_nodes)
                *(float2*)(g_hp + (size_t)(r0 + 8) * OUT_DIM + col) =
                    make_float2(d[mt][nt][2], d[mt][nt][3]);
        }
    }
}

// ---------------------------------------------------------------------------
// Kernel 5: pull-aggregate + bias + relu.
// 16 threads per dst node, each owns a float4 column slice. Unroll-by-8 edge
// loop for MLP=8 on the gather chain. Single plain store per node.
// ---------------------------------------------------------------------------
__global__ __launch_bounds__(256) void pull_kernel(const float* __restrict__ b,
                                                   float* __restrict__ out,
                                                   int n_nodes) {
    unsigned int t = blockIdx.x * blockDim.x + threadIdx.x;
    unsigned int node = t >> 4;
    if (node >= (unsigned int)n_nodes) return;
    int c4 = (t & 15) * 4;

    int deg = g_deg[node];
    if (deg > MAXDEG) deg = MAXDEG;
    const int* adj = g_adj + (size_t)node * MAXDEG;

    float4 acc = make_float4(0.f, 0.f, 0.f, 0.f);
    int e = 0;
    for (; e + 8 <= deg; e += 8) {
        int s0 = __ldg(adj + e + 0);
        int s1 = __ldg(adj + e + 1);
        int s2 = __ldg(adj + e + 2);
        int s3 = __ldg(adj + e + 3);
        int s4 = __ldg(adj + e + 4);
        int s5 = __ldg(adj + e + 5);
        int s6 = __ldg(adj + e + 6);
        int s7 = __ldg(adj + e + 7);
        float4 v0 = *(const float4*)(g_hp + (size_t)s0 * OUT_DIM + c4);
        float4 v1 = *(const float4*)(g_hp + (size_t)s1 * OUT_DIM + c4);
        float4 v2 = *(const float4*)(g_hp + (size_t)s2 * OUT_DIM + c4);
        float4 v3 = *(const float4*)(g_hp + (size_t)s3 * OUT_DIM + c4);
        float4 v4 = *(const float4*)(g_hp + (size_t)s4 * OUT_DIM + c4);
        float4 v5 = *(const float4*)(g_hp + (size_t)s5 * OUT_DIM + c4);
        float4 v6 = *(const float4*)(g_hp + (size_t)s6 * OUT_DIM + c4);
        float4 v7 = *(const float4*)(g_hp + (size_t)s7 * OUT_DIM + c4);
        acc.x += (v0.x + v1.x) + (v2.x + v3.x) + (v4.x + v5.x) + (v6.x + v7.x);
        acc.y += (v0.y + v1.y) + (v2.y + v3.y) + (v4.y + v5.y) + (v6.y + v7.y);
        acc.z += (v0.z + v1.z) + (v2.z + v3.z) + (v4.z + v5.z) + (v6.z + v7.z);
        acc.w += (v0.w + v1.w) + (v2.w + v3.w) + (v4.w + v5.w) + (v6.w + v7.w);
    }
    for (; e < deg; e++) {
        int s = __ldg(adj + e);
        float4 v = *(const float4*)(g_hp + (size_t)s * OUT_DIM + c4);
        acc.x += v.x; acc.y += v.y; acc.z += v.z; acc.w += v.w;
    }

    float4 bb = *(const float4*)(b + c4);
    acc.x = fmaxf(acc.x + bb.x, 0.f);
    acc.y = fmaxf(acc.y + bb.y, 0.f);
    acc.z = fmaxf(acc.z + bb.z, 0.f);
    acc.w = fmaxf(acc.w + bb.w, 0.f);
    *(float4*)(out + (size_t)node * OUT_DIM + c4) = acc;
}

// ---------------------------------------------------------------------------
// Launch
// inputs: 0=h [N,128] f32, 1=W [4,128,64] f32, 2=b [64] f32,
//         3=src [E] i32, 4=dst [E] i32 ; out: [N,64] f32
// ---------------------------------------------------------------------------
extern "C" void kernel_launch(void* const* d_in, const int* in_sizes, int n_in,
                              void* d_out, int out_size) {
    const float* h   = (const float*)d_in[0];
    const float* W   = (const float*)d_in[1];
    const float* b   = (const float*)d_in[2];
    const int*   src = (const int*)d_in[3];
    const int*   dst = (const int*)d_in[4];
    float* out = (float*)d_out;

    int n_nodes = in_sizes[0] / IN_DIM;    // 50000
    int n_edges = in_sizes[3];             // 800000

    // 1. Wavg -> tf32 hi/lo split
    wavg_kernel<<<(IN_DIM * OUT_DIM + 255) / 256, 256>>>(W);

    // 2. adjacency build (4 edges/thread)
    {
        int n4 = (n_nodes + 3) / 4;
        zero_deg_kernel<<<(n4 + 255) / 256, 256>>>(n4);
        int nG = n_edges / 4 + 1;
        build_adj_kernel<<<(nG + 255) / 256, 256>>>(src, dst, n_edges);
    }

    // 3. hp = h @ Wavg (tensor cores, 3xTF32)
    gemm_kernel<<<(n_nodes + BM - 1) / BM, 256>>>(h, n_nodes);

    // 4. pull-aggregate + bias + relu
    {
        long long threads = (long long)n_nodes * 16;
        int blocks = (int)((threads + 255) / 256);
        pull_kernel<<<blocks, 256>>>(b, out, n_nodes);
    }
}

// round 11
// speedup vs baseline: 1.0791x; 1.0791x over previous
#include <cuda_runtime.h>
#include <cuda_bf16.h>
#include <cstdint>

#define N_NODES 50000
#define N_EDGES 800000
#define IN_DIM 128
#define OUT_DIM 64
#define NUM_HEADS 4
#define MAXDEG 96

// Scratch (no cudaMalloc allowed)
__device__ float g_Whi[IN_DIM * OUT_DIM];           // tf32-rounded hi part of Wavg
__device__ float g_Wlo[IN_DIM * OUT_DIM];           // tf32-rounded residual
__device__ float g_hp[N_NODES * OUT_DIM];           // 12.8 MB
__device__ int   g_deg[N_NODES];                    // 200 KB
__device__ int   g_adj[(size_t)N_NODES * MAXDEG];   // 19.2 MB

// ---------------------------------------------------------------------------
// tf32 helpers
// ---------------------------------------------------------------------------
__device__ __forceinline__ void split_tf32(float x, uint32_t& hi, uint32_t& lo) {
    asm("cvt.rna.tf32.f32 %0, %1;" : "=r"(hi) : "f"(x));
    float r = x - __uint_as_float(hi);
    asm("cvt.rna.tf32.f32 %0, %1;" : "=r"(lo) : "f"(r));
}

#define MMA_TF32(D, A0, A1, A2, A3, B0, B1)                                    \
    asm("mma.sync.aligned.m16n8k8.row.col.f32.tf32.tf32.f32 "                  \
        "{%0,%1,%2,%3}, {%4,%5,%6,%7}, {%8,%9}, {%0,%1,%2,%3};"                \
        : "+f"((D)[0]), "+f"((D)[1]), "+f"((D)[2]), "+f"((D)[3])               \
        : "r"(A0), "r"(A1), "r"(A2), "r"(A3), "r"(B0), "r"(B1))

// ---------------------------------------------------------------------------
// Kernel 1: setup — Wavg tf32 hi/lo split + zero degree counters
// ---------------------------------------------------------------------------
__global__ void setup_kernel(const float* __restrict__ W, int n_nodes) {
    int i = blockIdx.x * blockDim.x + threadIdx.x;
    if (i < IN_DIM * OUT_DIM) {
        float avg = 0.25f * (W[i] + W[IN_DIM * OUT_DIM + i] +
                             W[2 * IN_DIM * OUT_DIM + i] + W[3 * IN_DIM * OUT_DIM + i]);
        uint32_t hi, lo;
        split_tf32(avg, hi, lo);
        g_Whi[i] = __uint_as_float(hi);
        g_Wlo[i] = __uint_as_float(lo);
    }
    // zero deg (grid-stride over int4)
    int n4 = n_nodes >> 2;
    for (int j = i; j < n4; j += gridDim.x * blockDim.x)
        ((int4*)g_deg)[j] = make_int4(0, 0, 0, 0);
    if (i < (n_nodes & 3)) g_deg[n4 * 4 + i] = 0;
}

// ---------------------------------------------------------------------------
// Kernel 2: FUSED heterogeneous kernel.
//   bid % 3 == 0  -> GEMM tile (hp = h @ Wavg via 3xTF32 mma)   [391 blocks]
//   otherwise     -> adjacency-build chunk (4 edges/thread)      [782 blocks]
// Interleaved so each wave mixes compute-bound and latency-bound CTAs; the
// adjacency blocks (issue ~5%) hide inside the GEMM's latency shadow.
// ---------------------------------------------------------------------------
#define BM 128
#define KPH 64
#define PA 68     // sA pitch in floats -> fragment bank = (4*gID + tig) % 32, all distinct

__global__ __launch_bounds__(256) void fused_kernel(const float* __restrict__ h,
                                                    const int* __restrict__ src,
                                                    const int* __restrict__ dst,
                                                    int n_nodes, int n_edges,
                                                    int n_gemm_blocks) {
    __shared__ float sA[BM * PA];    // ~34.8 KB (reserved for all blocks; used by GEMM role)

    int bid = blockIdx.x;
    int tid = threadIdx.x;

    if (bid % 3 != 0 || bid / 3 >= n_gemm_blocks) {
        // ---------------- adjacency role ----------------
        int adjId = bid - bid / 3 - 1;           // 0..781 for bid%3!=0
        if (bid % 3 == 0) adjId = bid;           // overflow gemm ids (none expected)
        int g = adjId * 256 + tid;               // edge group (4 edges)
        int nG = n_edges >> 2;
        if (g < nG) {
            int4 s = ((const int4*)src)[g];
            int4 d = ((const int4*)dst)[g];
            int p0 = atomicAdd(&g_deg[d.x], 1);
            int p1 = atomicAdd(&g_deg[d.y], 1);
            int p2 = atomicAdd(&g_deg[d.z], 1);
            int p3 = atomicAdd(&g_deg[d.w], 1);
            if (p0 < MAXDEG) g_adj[(size_t)d.x * MAXDEG + p0] = s.x;
            if (p1 < MAXDEG) g_adj[(size_t)d.y * MAXDEG + p1] = s.y;
            if (p2 < MAXDEG) g_adj[(size_t)d.z * MAXDEG + p2] = s.z;
            if (p3 < MAXDEG) g_adj[(size_t)d.w * MAXDEG + p3] = s.w;
        } else if (g == nG) {
            for (int e = nG * 4; e < n_edges; e++) {
                int d = dst[e];
                int pos = atomicAdd(&g_deg[d], 1);
                if (pos < MAXDEG) g_adj[(size_t)d * MAXDEG + pos] = src[e];
            }
        }
        return;
    }

    // ---------------- GEMM role ----------------
    int tile = bid / 3;
    int lane = tid & 31;
    int wid  = tid >> 5;       // 0..7
    int wm   = wid & 3;        // M strip: rows wm*32..wm*32+31
    int wn   = wid >> 2;       // N strip: cols wn*32..wn*32+31
    int gID  = lane >> 2;      // 0..7
    int tig  = lane & 3;       // 0..3
    int rowBase = tile * BM;

    float d[2][4][4];          // [mtile][ntile][frag]
    #pragma unroll
    for (int mt = 0; mt < 2; mt++)
        #pragma unroll
        for (int nt = 0; nt < 4; nt++)
            #pragma unroll
            for (int q = 0; q < 4; q++) d[mt][nt][q] = 0.f;

    #pragma unroll
    for (int ph = 0; ph < 2; ph++) {
        // stage h slab: 128 rows x 64 floats = 2048 float4, 8 per thread
        #pragma unroll
        for (int it = 0; it < 8; it++) {
            int item = tid + it * 256;
            int r = item >> 4;          // 16 float4 per row
            int c = item & 15;
            int row = rowBase + r;
            float4 v = make_float4(0.f, 0.f, 0.f, 0.f);
            if (row < n_nodes)
                v = ((const float4*)(h + (size_t)row * IN_DIM + ph * KPH))[c];
            *(float4*)(sA + r * PA + 4 * c) = v;
        }
        __syncthreads();

        #pragma unroll
        for (int kk = 0; kk < KPH; kk += 8) {
            int kg = ph * KPH + kk + tig;    // global k of b0 row

            // B fragments hi/lo for 4 n-tiles (L1-resident __ldg)
            uint32_t bhi[4][2], blo[4][2];
            #pragma unroll
            for (int nt = 0; nt < 4; nt++) {
                int ncol = wn * 32 + nt * 8 + gID;
                int i0 = kg * OUT_DIM + ncol;
                int i1 = (kg + 4) * OUT_DIM + ncol;
                bhi[nt][0] = __float_as_uint(__ldg(g_Whi + i0));
                bhi[nt][1] = __float_as_uint(__ldg(g_Whi + i1));
                blo[nt][0] = __float_as_uint(__ldg(g_Wlo + i0));
                blo[nt][1] = __float_as_uint(__ldg(g_Wlo + i1));
            }

            #pragma unroll
            for (int mt = 0; mt < 2; mt++) {
                const float* ab = sA + (wm * 32 + mt * 16 + gID) * PA + kk + tig;
                float a0 = ab[0];
                float a1 = ab[8 * PA];
                float a2 = ab[4];
                float a3 = ab[8 * PA + 4];
                uint32_t ah[4], al[4];
                split_tf32(a0, ah[0], al[0]);
                split_tf32(a1, ah[1], al[1]);
                split_tf32(a2, ah[2], al[2]);
                split_tf32(a3, ah[3], al[3]);

                #pragma unroll
                for (int nt = 0; nt < 4; nt++) {
                    MMA_TF32(d[mt][nt], ah[0], ah[1], ah[2], ah[3],
                             bhi[nt][0], bhi[nt][1]);
                    MMA_TF32(d[mt][nt], al[0], al[1], al[2], al[3],
                             bhi[nt][0], bhi[nt][1]);
                    MMA_TF32(d[mt][nt], ah[0], ah[1], ah[2], ah[3],
                             blo[nt][0], blo[nt][1]);
                }
            }
        }
        __syncthreads();
    }

    // epilogue
    #pragma unroll
    for (int mt = 0; mt < 2; mt++) {
        int r0 = rowBase + wm * 32 + mt * 16 + gID;
        #pragma unroll
        for (int nt = 0; nt < 4; nt++) {
            int col = wn * 32 + nt * 8 + tig * 2;
            if (r0 < n_nodes)
                *(float2*)(g_hp + (size_t)r0 * OUT_DIM + col) =
                    make_float2(d[mt][nt][0], d[mt][nt][1]);
            if (r0 + 8 < n_nodes)
                *(float2*)(g_hp + (size_t)(r0 + 8) * OUT_DIM + col) =
                    make_float2(d[mt][nt][2], d[mt][nt][3]);
        }
    }
}

// ---------------------------------------------------------------------------
// Kernel 3: pull-aggregate + bias + relu.
// ---------------------------------------------------------------------------
__global__ __launch_bounds__(256) void pull_kernel(const float* __restrict__ b,
                                                   float* __restrict__ out,
                                                   int n_nodes) {
    unsigned int t = blockIdx.x * blockDim.x + threadIdx.x;
    unsigned int node = t >> 4;
    if (node >= (unsigned int)n_nodes) return;
    int c4 = (t & 15) * 4;

    int deg = g_deg[node];
    if (deg > MAXDEG) deg = MAXDEG;
    const int* adj = g_adj + (size_t)node * MAXDEG;

    float4 acc = make_float4(0.f, 0.f, 0.f, 0.f);
    int e = 0;
    for (; e + 8 <= deg; e += 8) {
        int s0 = __ldg(adj + e + 0);
        int s1 = __ldg(adj + e + 1);
        int s2 = __ldg(adj + e + 2);
        int s3 = __ldg(adj + e + 3);
        int s4 = __ldg(adj + e + 4);
        int s5 = __ldg(adj + e + 5);
        int s6 = __ldg(adj + e + 6);
        int s7 = __ldg(adj + e + 7);
        float4 v0 = *(const float4*)(g_hp + (size_t)s0 * OUT_DIM + c4);
        float4 v1 = *(const float4*)(g_hp + (size_t)s1 * OUT_DIM + c4);
        float4 v2 = *(const float4*)(g_hp + (size_t)s2 * OUT_DIM + c4);
        float4 v3 = *(const float4*)(g_hp + (size_t)s3 * OUT_DIM + c4);
        float4 v4 = *(const float4*)(g_hp + (size_t)s4 * OUT_DIM + c4);
        float4 v5 = *(const float4*)(g_hp + (size_t)s5 * OUT_DIM + c4);
        float4 v6 = *(const float4*)(g_hp + (size_t)s6 * OUT_DIM + c4);
        float4 v7 = *(const float4*)(g_hp + (size_t)s7 * OUT_DIM + c4);
        acc.x += (v0.x + v1.x) + (v2.x + v3.x) + (v4.x + v5.x) + (v6.x + v7.x);
        acc.y += (v0.y + v1.y) + (v2.y + v3.y) + (v4.y + v5.y) + (v6.y + v7.y);
        acc.z += (v0.z + v1.z) + (v2.z + v3.z) + (v4.z + v5.z) + (v6.z + v7.z);
        acc.w += (v0.w + v1.w) + (v2.w + v3.w) + (v4.w + v5.w) + (v6.w + v7.w);
    }
    for (; e < deg; e++) {
        int s = __ldg(adj + e);
        float4 v = *(const float4*)(g_hp + (size_t)s * OUT_DIM + c4);
        acc.x += v.x; acc.y += v.y; acc.z += v.z; acc.w += v.w;
    }

    float4 bb = *(const float4*)(b + c4);
    acc.x = fmaxf(acc.x + bb.x, 0.f);
    acc.y = fmaxf(acc.y + bb.y, 0.f);
    acc.z = fmaxf(acc.z + bb.z, 0.f);
    acc.w = fmaxf(acc.w + bb.w, 0.f);
    *(float4*)(out + (size_t)node * OUT_DIM + c4) = acc;
}

// ---------------------------------------------------------------------------
// Launch
// inputs: 0=h [N,128] f32, 1=W [4,128,64] f32, 2=b [64] f32,
//         3=src [E] i32, 4=dst [E] i32 ; out: [N,64] f32
// ---------------------------------------------------------------------------
extern "C" void kernel_launch(void* const* d_in, const int* in_sizes, int n_in,
                              void* d_out, int out_size) {
    const float* h   = (const float*)d_in[0];
    const float* W   = (const float*)d_in[1];
    const float* b   = (const float*)d_in[2];
    const int*   src = (const int*)d_in[3];
    const int*   dst = (const int*)d_in[4];
    float* out = (float*)d_out;

    int n_nodes = in_sizes[0] / IN_DIM;    // 50000
    int n_edges = in_sizes[3];             // 800000

    // 1. setup: Wavg tf32 split + zero deg
    setup_kernel<<<64, 256>>>(W, n_nodes);

    // 2. fused GEMM + adjacency build
    {
        int n_gemm = (n_nodes + BM - 1) / BM;                 // 391
        int nGroups = n_edges / 4 + 1;                        // 200001
        int n_adj = (nGroups + 255) / 256;                    // 782
        // grid: every 3rd block is a GEMM tile; need max(3*n_gemm-2, ...) to
        // cover both roles. adjId = bid - bid/3 - 1 for bid%3!=0.
        int grid = 3 * n_gemm;                                // 1173 -> 391 gemm, 782 adj
        // ensure adjacency coverage: adj blocks available = grid - n_gemm
        if (grid - n_gemm < n_adj) grid = n_gemm + n_adj + (n_gemm + n_adj) / 2 + 2;
        fused_kernel<<<grid, 256>>>(h, src, dst, n_nodes, n_edges, n_gemm);
    }

    // 3. pull-aggregate + bias + relu
    {
        long long threads = (long long)n_nodes * 16;
        int blocks = (int)((threads + 255) / 256);
        pull_kernel<<<blocks, 256>>>(b, out, n_nodes);
    }
}